// round 1
// baseline (speedup 1.0000x reference)
#include <cuda_runtime.h>
#include <cuda_fp16.h>
#include <cstdint>

#define BB 64
#define FF 4
#define MM 4096
#define DD 1024
#define NITER 15
#define WD 16   // DD/64 words of sign bits

// ---------------- device scratch (static allocation, no cudaMalloc) ----------------
__device__ unsigned long long g_est[BB * FF * WD];        // estimate sign bits (1 = negative)
__device__ unsigned long long g_in[BB * WD];              // input sign bits
__device__ unsigned long long g_cbD[FF * MM * WD];        // codebook bits packed along d
__device__ __half             g_cb16[(size_t)FF * MM * DD]; // codebook as fp16 (+-1), row-major [f][m][d]
__device__ __half             g_sim[(size_t)FF * BB * MM];  // sim as fp16, row-major [f][b][m]
__device__ int                g_mismatch[NITER];

// ---------------- helpers ----------------
__device__ __forceinline__ uint32_t smem_u32(const void* p) {
    return (uint32_t)__cvta_generic_to_shared(p);
}

__device__ __forceinline__ void ldm_x4(uint32_t& r0, uint32_t& r1, uint32_t& r2, uint32_t& r3, uint32_t addr) {
    asm volatile("ldmatrix.sync.aligned.m8n8.x4.shared.b16 {%0,%1,%2,%3}, [%4];\n"
                 : "=r"(r0), "=r"(r1), "=r"(r2), "=r"(r3) : "r"(addr));
}

__device__ __forceinline__ void ldm_x4_t(uint32_t& r0, uint32_t& r1, uint32_t& r2, uint32_t& r3, uint32_t addr) {
    asm volatile("ldmatrix.sync.aligned.m8n8.x4.trans.shared.b16 {%0,%1,%2,%3}, [%4];\n"
                 : "=r"(r0), "=r"(r1), "=r"(r2), "=r"(r3) : "r"(addr));
}

__device__ __forceinline__ void mma16816(float* c, uint32_t a0, uint32_t a1, uint32_t a2, uint32_t a3,
                                         uint32_t b0, uint32_t b1) {
    asm volatile("mma.sync.aligned.m16n8k16.row.col.f32.f16.f16.f32 "
                 "{%0,%1,%2,%3}, {%4,%5,%6,%7}, {%8,%9}, {%0,%1,%2,%3};\n"
                 : "+f"(c[0]), "+f"(c[1]), "+f"(c[2]), "+f"(c[3])
                 : "r"(a0), "r"(a1), "r"(a2), "r"(a3), "r"(b0), "r"(b1));
}

// ---------------- pack kernels ----------------
// one warp per row; row = codebook row (f*MM + m), 1024 floats -> 16 u64 bits + 1024 halves
__global__ void k_pack_cb(const float* __restrict__ cb) {
    int row  = blockIdx.x * 4 + (threadIdx.x >> 5);
    int lane = threadIdx.x & 31;
    const float* src = cb + (size_t)row * DD;
    unsigned long long lo = 0;
    #pragma unroll
    for (int i = 0; i < 32; i++) {
        int d = i * 32 + lane;
        float v = src[d];
        g_cb16[(size_t)row * DD + d] = __float2half_rn(v);
        unsigned bal = __ballot_sync(0xffffffffu, v < 0.f);
        if ((i & 1) == 0) lo = bal;
        else if (lane == 0) g_cbD[row * WD + (i >> 1)] = lo | ((unsigned long long)bal << 32);
    }
}

// rows 0..255 = init estimates (b*4+f), rows 256..319 = input rows
__global__ void k_pack_est(const float* __restrict__ inp, const float* __restrict__ est0) {
    int row  = blockIdx.x * 4 + (threadIdx.x >> 5);
    int lane = threadIdx.x & 31;
    if (blockIdx.x == 0 && threadIdx.x < NITER) g_mismatch[threadIdx.x] = 0;
    const float* src;
    unsigned long long* dst;
    if (row < BB * FF) { src = est0 + (size_t)row * DD; dst = g_est + row * WD; }
    else               { int b = row - BB * FF; src = inp + (size_t)b * DD; dst = g_in + b * WD; }
    unsigned long long lo = 0;
    #pragma unroll
    for (int i = 0; i < 32; i++) {
        unsigned bal = __ballot_sync(0xffffffffu, src[i * 32 + lane] < 0.f);
        if ((i & 1) == 0) lo = bal;
        else if (lane == 0) dst[i >> 1] = lo | ((unsigned long long)bal << 32);
    }
}

// ---------------- per-iteration: sim via XOR+POPC ----------------
// block = (b, f); sim[b,f,m] = DD - 2*popc(new_est ^ cb), new_est = in ^ (xor of all est) ^ est[f]
__global__ void k_sim() {
    int b = blockIdx.x >> 2, f = blockIdx.x & 3;
    __shared__ unsigned long long ne[WD];
    int t = threadIdx.x;
    if (t < WD) {
        unsigned long long x = g_in[b * WD + t];
        x ^= g_est[(b * FF + 0) * WD + t] ^ g_est[(b * FF + 1) * WD + t]
           ^ g_est[(b * FF + 2) * WD + t] ^ g_est[(b * FF + 3) * WD + t];
        x ^= g_est[(b * FF + f) * WD + t];   // remove own factor (e*e = 1)
        ne[t] = x;
    }
    __syncthreads();
    unsigned long long r[WD];
    #pragma unroll
    for (int w = 0; w < WD; w++) r[w] = ne[w];
    const unsigned long long* cb = g_cbD + (size_t)f * MM * WD;
    __half* out = g_sim + (size_t)(f * BB + b) * MM;
    for (int m = t; m < MM; m += 128) {
        const unsigned long long* rowp = cb + (size_t)m * WD;
        int h = 0;
        #pragma unroll
        for (int w = 0; w < WD; w++) h += __popcll(r[w] ^ rowp[w]);
        out[m] = __float2half_rn((float)(DD - 2 * h));   // |sim|<=1024, exact in fp16
    }
}

// ---------------- per-iteration: GEMM2 (fp16 HMMA) + sign + pack + convergence ----------------
// block = (f, n-tile of 64 d's). A = sim[f] (64 x 4096 fp16), B = cb16[f] (4096 x 1024 fp16)
__global__ void k_gemm2(int iter) {
    int f  = blockIdx.x >> 4;
    int n0 = (blockIdx.x & 15) << 6;
    int t = threadIdx.x, lane = t & 31, w = t >> 5;

    __shared__ __align__(16) __half sA[64 * 64];
    __shared__ __align__(16) __half sB[64 * 64];
    __shared__ float sC[64][65];

    float acc[8][4];
    #pragma unroll
    for (int j = 0; j < 8; j++)
        #pragma unroll
        for (int q = 0; q < 4; q++) acc[j][q] = 0.f;

    const __half* gA = g_sim  + (size_t)f * BB * MM;
    const __half* gB = g_cb16 + (size_t)f * MM * DD + n0;

    for (int k0 = 0; k0 < MM; k0 += 64) {
        // cooperative load of 64x64 A and B tiles, XOR-swizzled smem (conflict-free ldmatrix)
        #pragma unroll
        for (int i = 0; i < 4; i++) {
            int chunk = i * 128 + t;            // 0..511
            int r = chunk >> 3, c8 = chunk & 7;
            uint4 va = *(const uint4*)(gA + (size_t)r * MM + k0 + c8 * 8);
            *(uint4*)(sA + r * 64 + ((c8 ^ (r & 7)) << 3)) = va;
            uint4 vb = *(const uint4*)(gB + (size_t)(k0 + r) * DD + c8 * 8);
            *(uint4*)(sB + r * 64 + ((c8 ^ (r & 7)) << 3)) = vb;
        }
        __syncthreads();

        #pragma unroll
        for (int kk = 0; kk < 4; kk++) {
            int ar  = w * 16 + (lane & 15);
            int ac8 = kk * 2 + (lane >> 4);
            uint32_t a0, a1, a2, a3;
            ldm_x4(a0, a1, a2, a3, smem_u32(sA + ar * 64 + ((ac8 ^ (ar & 7)) << 3)));
            #pragma unroll
            for (int j2 = 0; j2 < 4; j2++) {
                int br  = kk * 16 + (lane & 15);
                int bc8 = j2 * 2 + (lane >> 4);
                uint32_t b0, b1, b2, b3;
                ldm_x4_t(b0, b1, b2, b3, smem_u32(sB + br * 64 + ((bc8 ^ (br & 7)) << 3)));
                mma16816(acc[j2 * 2],     a0, a1, a2, a3, b0, b1);
                mma16816(acc[j2 * 2 + 1], a0, a1, a2, a3, b2, b3);
            }
        }
        __syncthreads();
    }

    // write fp32 bundle to smem
    int r0 = w * 16 + (lane >> 2), c0 = (lane & 3) * 2;
    #pragma unroll
    for (int j = 0; j < 8; j++) {
        sC[r0][j * 8 + c0]         = acc[j][0];
        sC[r0][j * 8 + c0 + 1]     = acc[j][1];
        sC[r0 + 8][j * 8 + c0]     = acc[j][2];
        sC[r0 + 8][j * 8 + c0 + 1] = acc[j][3];
    }
    __syncthreads();

    // sign -> bit (bit=1 means value -1; sign(0)=+1 -> strict <0), pack, compare, count mismatches
    if (t < 64) {
        unsigned long long word = 0;
        #pragma unroll
        for (int j = 0; j < 64; j++)
            if (sC[t][j] < 0.f) word |= 1ULL << j;
        int widx = n0 >> 6;
        unsigned long long* ep = g_est + (size_t)(t * FF + f) * WD + widx;
        unsigned long long old = *ep;
        *ep = word;
        unsigned mask = __ballot_sync(0xffffffffu, word != old);
        if (lane == 0 && mask) atomicAdd(&g_mismatch[iter], __popc(mask));
    }
}

// ---------------- final: cleanup argmax|sim|, est floats, iters/conv ----------------
__global__ void k_final(float* __restrict__ out, int out_size) {
    int b = blockIdx.x >> 2, f = blockIdx.x & 3;
    int t = threadIdx.x;
    unsigned long long e[WD];
    #pragma unroll
    for (int w = 0; w < WD; w++) e[w] = g_est[(size_t)(b * FF + f) * WD + w];

    const unsigned long long* cb = g_cbD + (size_t)f * MM * WD;
    int bestA = -1, bestI = 0;
    for (int m = t; m < MM; m += 128) {
        const unsigned long long* rowp = cb + (size_t)m * WD;
        int h = 0;
        #pragma unroll
        for (int w = 0; w < WD; w++) h += __popcll(e[w] ^ rowp[w]);
        int s = DD - 2 * h;
        int a = s < 0 ? -s : s;
        if (a > bestA) { bestA = a; bestI = m; }   // ascending m keeps first argmax
    }
    __shared__ int sAv[128], sIv[128];
    sAv[t] = bestA; sIv[t] = bestI;
    __syncthreads();
    for (int off = 64; off; off >>= 1) {
        if (t < off) {
            int a2 = sAv[t + off], i2 = sIv[t + off];
            if (a2 > sAv[t] || (a2 == sAv[t] && i2 < sIv[t])) { sAv[t] = a2; sIv[t] = i2; }
        }
        __syncthreads();
    }
    int idx = b * FF + f;
    if (t == 0 && idx < out_size) out[idx] = (float)sIv[0];

    if (out_size >= 256 + BB * FF * DD) {
        float* oe = out + 256 + (size_t)idx * DD;
        for (int d = t; d < DD; d += 128) {
            int bit = (int)((e[d >> 6] >> (d & 63)) & 1ULL);
            oe[d] = bit ? -1.f : 1.f;
        }
    }
    if (blockIdx.x == 0 && t == 0 && out_size >= 256 + BB * FF * DD + 2) {
        int iters = NITER, conv = 0;
        for (int tt = 0; tt < NITER; tt++)
            if (g_mismatch[tt] == 0) { iters = tt + 1; conv = 1; break; }
        out[256 + BB * FF * DD]     = (float)iters;
        out[256 + BB * FF * DD + 1] = (float)conv;
    }
}

// ---------------- launch ----------------
extern "C" void kernel_launch(void* const* d_in, const int* in_sizes, int n_in,
                              void* d_out, int out_size) {
    const float* input = nullptr;
    const float* est0  = nullptr;
    const float* cb    = nullptr;
    for (int i = 0; i < n_in; i++) {
        if (in_sizes[i] == BB * DD)            input = (const float*)d_in[i];
        else if (in_sizes[i] == BB * FF * DD)  est0  = (const float*)d_in[i];
        else if (in_sizes[i] == FF * MM * DD)  cb    = (const float*)d_in[i];
    }
    k_pack_est<<<80, 128>>>(input, est0);
    k_pack_cb<<<FF * MM / 4, 128>>>(cb);
    for (int it = 0; it < NITER; it++) {
        k_sim<<<BB * FF, 128>>>();
        k_gemm2<<<64, 128>>>(it);
    }
    k_final<<<BB * FF, 128>>>((float*)d_out, out_size);
}

// round 2
// speedup vs baseline: 6.4513x; 6.4513x over previous
#include <cuda_runtime.h>
#include <cuda_fp16.h>
#include <cstdint>

typedef unsigned long long ull;

#define BB 64
#define FF 4
#define MM 4096
#define DD 1024
#define NITER 15
#define WD 16   // DD/64 sign-bit words

// ---------------- device scratch ----------------
__device__ ull g_est[2][BB * FF * WD];               // ping-pong estimate bits (1 = negative)
__device__ ull g_in[BB * WD];                        // input bits
__device__ ull g_cbD[FF * MM * WD];                  // codebook bits (for final cleanup)
__device__ __align__(16) __half g_cb16[(size_t)FF * MM * DD];  // codebook fp16
__device__ __align__(16) __half g_G[(size_t)FF * DD * DD];     // Gram: G[f] = C[f]^T C[f] (even ints, fp16-exact)
__device__ int g_mismatch[NITER];

// ---------------- helpers ----------------
__device__ __forceinline__ uint32_t smem_u32(const void* p) {
    return (uint32_t)__cvta_generic_to_shared(p);
}
__device__ __forceinline__ void ldm_x4(uint32_t& r0, uint32_t& r1, uint32_t& r2, uint32_t& r3, uint32_t addr) {
    asm volatile("ldmatrix.sync.aligned.m8n8.x4.shared.b16 {%0,%1,%2,%3}, [%4];\n"
                 : "=r"(r0), "=r"(r1), "=r"(r2), "=r"(r3) : "r"(addr));
}
__device__ __forceinline__ void ldm_x4_t(uint32_t& r0, uint32_t& r1, uint32_t& r2, uint32_t& r3, uint32_t addr) {
    asm volatile("ldmatrix.sync.aligned.m8n8.x4.trans.shared.b16 {%0,%1,%2,%3}, [%4];\n"
                 : "=r"(r0), "=r"(r1), "=r"(r2), "=r"(r3) : "r"(addr));
}
__device__ __forceinline__ void mma16816(float* c, uint32_t a0, uint32_t a1, uint32_t a2, uint32_t a3,
                                         uint32_t b0, uint32_t b1) {
    asm volatile("mma.sync.aligned.m16n8k16.row.col.f32.f16.f16.f32 "
                 "{%0,%1,%2,%3}, {%4,%5,%6,%7}, {%8,%9}, {%0,%1,%2,%3};\n"
                 : "+f"(c[0]), "+f"(c[1]), "+f"(c[2]), "+f"(c[3])
                 : "r"(a0), "r"(a1), "r"(a2), "r"(a3), "r"(b0), "r"(b1));
}

// ---------------- pack kernels ----------------
__global__ void k_pack_cb(const float* __restrict__ cb) {
    int row  = blockIdx.x * 4 + (threadIdx.x >> 5);
    int lane = threadIdx.x & 31;
    const float* src = cb + (size_t)row * DD;
    ull lo = 0;
    #pragma unroll
    for (int i = 0; i < 32; i++) {
        int d = i * 32 + lane;
        float v = src[d];
        g_cb16[(size_t)row * DD + d] = __float2half_rn(v);
        unsigned bal = __ballot_sync(0xffffffffu, v < 0.f);
        if ((i & 1) == 0) lo = bal;
        else if (lane == 0) g_cbD[row * WD + (i >> 1)] = lo | ((ull)bal << 32);
    }
}

__global__ void k_pack_est(const float* __restrict__ inp, const float* __restrict__ est0) {
    int row  = blockIdx.x * 4 + (threadIdx.x >> 5);
    int lane = threadIdx.x & 31;
    if (blockIdx.x == 0 && threadIdx.x < NITER) g_mismatch[threadIdx.x] = 0;
    const float* src;
    ull* dst;
    if (row < BB * FF) { src = est0 + (size_t)row * DD; dst = g_est[0] + row * WD; }
    else               { int b = row - BB * FF; src = inp + (size_t)b * DD; dst = g_in + b * WD; }
    ull lo = 0;
    #pragma unroll
    for (int i = 0; i < 32; i++) {
        unsigned bal = __ballot_sync(0xffffffffu, src[i * 32 + lane] < 0.f);
        if ((i & 1) == 0) lo = bal;
        else if (lane == 0) dst[i >> 1] = lo | ((ull)bal << 32);
    }
}

// ---------------- Gram matrix: G[f][d][d'] = sum_m C[m,d]*C[m,d'] ----------------
// grid = 4 * 36 upper-triangle 128x128 tiles. K = 4096, chunks of 32.
__global__ void k_gram() {
    int f = blockIdx.x / 36, pair = blockIdx.x % 36;
    int i = 0, rem = pair;
    while (rem >= 8 - i) { rem -= 8 - i; i++; }
    int j = i + rem;
    int gi = i << 7, gj = j << 7;
    int t = threadIdx.x, lane = t & 31, w = t >> 5;
    int wm = w >> 1, wn = w & 1;            // warp tile 32m x 64n

    __shared__ __align__(16) __half sI[2][32 * 128];
    __shared__ __align__(16) __half sJ[2][32 * 128];

    const __half* Cf = g_cb16 + (size_t)f * MM * DD;

    float acc[2][8][4];
    #pragma unroll
    for (int a = 0; a < 2; a++)
        #pragma unroll
        for (int b2 = 0; b2 < 8; b2++)
            #pragma unroll
            for (int q = 0; q < 4; q++) acc[a][b2][q] = 0.f;

    uint4 rI[2], rJ[2];
    #pragma unroll
    for (int q = 0; q < 2; q++) {
        int id = t * 2 + q, r = id >> 4, cc = id & 15;
        rI[q] = *(const uint4*)(Cf + (size_t)r * DD + gi + cc * 8);
        rJ[q] = *(const uint4*)(Cf + (size_t)r * DD + gj + cc * 8);
    }
    #pragma unroll
    for (int q = 0; q < 2; q++) {
        int id = t * 2 + q, r = id >> 4, cc = id & 15, sub = cc >> 3, c8 = cc & 7;
        *(uint4*)(&sI[0][sub * 2048 + r * 64 + ((c8 ^ (r & 7)) << 3)]) = rI[q];
        *(uint4*)(&sJ[0][sub * 2048 + r * 64 + ((c8 ^ (r & 7)) << 3)]) = rJ[q];
    }

    for (int c = 0; c < 128; c++) {
        if (c + 1 < 128) {
            int k0 = (c + 1) * 32;
            #pragma unroll
            for (int q = 0; q < 2; q++) {
                int id = t * 2 + q, r = id >> 4, cc = id & 15;
                rI[q] = *(const uint4*)(Cf + (size_t)(k0 + r) * DD + gi + cc * 8);
                rJ[q] = *(const uint4*)(Cf + (size_t)(k0 + r) * DD + gj + cc * 8);
            }
        }
        __syncthreads();
        const __half* bI = sI[c & 1];
        const __half* bJ = sJ[c & 1];
        #pragma unroll
        for (int k16 = 0; k16 < 2; k16++) {
            uint32_t a_[2][4];
            #pragma unroll
            for (int mi = 0; mi < 2; mi++) {
                int col = wm * 32 + mi * 16;
                int sub = col >> 6, cl = col & 63;
                int rr = k16 * 16 + (lane & 15);
                int cc8 = (cl >> 3) + (lane >> 4);
                ldm_x4_t(a_[mi][0], a_[mi][1], a_[mi][2], a_[mi][3],
                         smem_u32(bI + sub * 2048 + rr * 64 + ((cc8 ^ (rr & 7)) << 3)));
            }
            #pragma unroll
            for (int ni = 0; ni < 4; ni++) {
                int col = wn * 64 + ni * 16;
                int sub = col >> 6, cl = col & 63;
                int rr = k16 * 16 + (lane & 15);
                int cc8 = (cl >> 3) + (lane >> 4);
                uint32_t b0, b1, b2, b3;
                ldm_x4_t(b0, b1, b2, b3,
                         smem_u32(bJ + sub * 2048 + rr * 64 + ((cc8 ^ (rr & 7)) << 3)));
                #pragma unroll
                for (int mi = 0; mi < 2; mi++) {
                    // A via trans-ldmatrix: register order (r0, r2, r1, r3)
                    mma16816(acc[mi][ni * 2],     a_[mi][0], a_[mi][2], a_[mi][1], a_[mi][3], b0, b1);
                    mma16816(acc[mi][ni * 2 + 1], a_[mi][0], a_[mi][2], a_[mi][1], a_[mi][3], b2, b3);
                }
            }
        }
        if (c + 1 < 128) {
            int buf = (c + 1) & 1;
            #pragma unroll
            for (int q = 0; q < 2; q++) {
                int id = t * 2 + q, r = id >> 4, cc = id & 15, sub = cc >> 3, c8 = cc & 7;
                *(uint4*)(&sI[buf][sub * 2048 + r * 64 + ((c8 ^ (r & 7)) << 3)]) = rI[q];
                *(uint4*)(&sJ[buf][sub * 2048 + r * 64 + ((c8 ^ (r & 7)) << 3)]) = rJ[q];
            }
        }
    }

    __half* Gf = g_G + (size_t)f * DD * DD;
    #pragma unroll
    for (int mi = 0; mi < 2; mi++)
        #pragma unroll
        for (int nf = 0; nf < 8; nf++) {
            int row = gi + wm * 32 + mi * 16 + (lane >> 2);
            int col = gj + wn * 64 + nf * 8 + (lane & 3) * 2;
            float* cc = acc[mi][nf];
            *(__half2*)&Gf[(size_t)row * DD + col]       = __floats2half2_rn(cc[0], cc[1]);
            *(__half2*)&Gf[(size_t)(row + 8) * DD + col] = __floats2half2_rn(cc[2], cc[3]);
            if (i != j) {
                Gf[(size_t)col * DD + row]           = __float2half_rn(cc[0]);
                Gf[(size_t)(col + 1) * DD + row]     = __float2half_rn(cc[1]);
                Gf[(size_t)col * DD + row + 8]       = __float2half_rn(cc[2]);
                Gf[(size_t)(col + 1) * DD + row + 8] = __float2half_rn(cc[3]);
            }
        }
}

// ---------------- per-iteration: upd = sign(new_est @ G), fused sign/pack/converge ----------------
// grid = 4 factors * 16 n-tiles of 64. block 256 (8 warps, warp = 16m x 32n). K = 1024.
__global__ void k_step(int iter) {
    int f  = blockIdx.x >> 4;
    int n0 = (blockIdx.x & 15) << 6;
    int t = threadIdx.x, lane = t & 31, w = t >> 5;
    int wm = w >> 1, wn = w & 1;
    int p = iter & 1;

    __shared__ __align__(16) unsigned char raw[8192 + 16384 + 16384];
    ull*    sBits = (ull*)raw;                        // [64][16]
    __half* sA    = (__half*)(raw + 8192);            // [2][64*64]
    __half* sB    = (__half*)(raw + 8192 + 16384);    // [2][64*64]
    float*  sC    = (float*)raw;                      // alias, [64][68]

    // new_est bits: in ^ (xor of all est) ^ est_f
    const ull* E = g_est[p];
    for (int idx = t; idx < 1024; idx += 256) {
        int b = idx >> 4, wd = idx & 15;
        ull x = g_in[b * WD + wd];
        x ^= E[(b * FF + 0) * WD + wd] ^ E[(b * FF + 1) * WD + wd]
           ^ E[(b * FF + 2) * WD + wd] ^ E[(b * FF + 3) * WD + wd];
        sBits[idx] = x ^ E[(b * FF + f) * WD + wd];
    }

    const __half* Gf = g_G + (size_t)f * DD * DD + n0;
    uint4 rB[2];
    #pragma unroll
    for (int q = 0; q < 2; q++) {
        int id = t * 2 + q, r = id >> 3, c8 = id & 7;
        rB[q] = *(const uint4*)(Gf + (size_t)r * DD + c8 * 8);
    }
    __syncthreads();   // bits visible

    // STS chunk 0 (B) + gen A chunk 0
    #pragma unroll
    for (int q = 0; q < 2; q++) {
        int id = t * 2 + q, r = id >> 3, c8 = id & 7;
        int so = r * 64 + ((c8 ^ (r & 7)) << 3);
        *(uint4*)(&sB[so]) = rB[q];
        ull word = sBits[r * WD + 0];
        uint32_t u[4];
        #pragma unroll
        for (int jj = 0; jj < 4; jj++) {
            uint32_t b0 = (uint32_t)((word >> (c8 * 8 + jj * 2)) & 1ull);
            uint32_t b1 = (uint32_t)((word >> (c8 * 8 + jj * 2 + 1)) & 1ull);
            u[jj] = 0x3C003C00u | (b0 << 15) | (b1 << 31);
        }
        *(uint4*)(&sA[so]) = *(uint4*)u;
    }

    float acc[4][4];
    #pragma unroll
    for (int a = 0; a < 4; a++)
        #pragma unroll
        for (int q = 0; q < 4; q++) acc[a][q] = 0.f;

    for (int c = 0; c < 16; c++) {
        if (c + 1 < 16) {
            #pragma unroll
            for (int q = 0; q < 2; q++) {
                int id = t * 2 + q, r = id >> 3, c8 = id & 7;
                rB[q] = *(const uint4*)(Gf + (size_t)((c + 1) * 64 + r) * DD + c8 * 8);
            }
        }
        __syncthreads();
        const __half* bA = sA + (c & 1) * 4096;
        const __half* bB = sB + (c & 1) * 4096;
        #pragma unroll
        for (int k16 = 0; k16 < 4; k16++) {
            uint32_t a0, a1, a2, a3;
            int ar  = wm * 16 + (lane & 15);
            int ac8 = k16 * 2 + (lane >> 4);
            ldm_x4(a0, a1, a2, a3, smem_u32(bA + ar * 64 + ((ac8 ^ (ar & 7)) << 3)));
            #pragma unroll
            for (int ni = 0; ni < 2; ni++) {
                int br  = k16 * 16 + (lane & 15);
                int bc8 = wn * 4 + ni * 2 + (lane >> 4);
                uint32_t b0, b1, b2, b3;
                ldm_x4_t(b0, b1, b2, b3, smem_u32(bB + br * 64 + ((bc8 ^ (br & 7)) << 3)));
                mma16816(acc[ni * 2],     a0, a1, a2, a3, b0, b1);
                mma16816(acc[ni * 2 + 1], a0, a1, a2, a3, b2, b3);
            }
        }
        if (c + 1 < 16) {
            int buf = (c + 1) & 1;
            #pragma unroll
            for (int q = 0; q < 2; q++) {
                int id = t * 2 + q, r = id >> 3, c8 = id & 7;
                int so = buf * 4096 + r * 64 + ((c8 ^ (r & 7)) << 3);
                *(uint4*)(&sB[so]) = rB[q];
                ull word = sBits[r * WD + (c + 1)];
                uint32_t u[4];
                #pragma unroll
                for (int jj = 0; jj < 4; jj++) {
                    uint32_t b0 = (uint32_t)((word >> (c8 * 8 + jj * 2)) & 1ull);
                    uint32_t b1 = (uint32_t)((word >> (c8 * 8 + jj * 2 + 1)) & 1ull);
                    u[jj] = 0x3C003C00u | (b0 << 15) | (b1 << 31);
                }
                *(uint4*)(&sA[so]) = *(uint4*)u;
            }
        }
    }
    __syncthreads();

    // stage fp32 results
    {
        int r0 = wm * 16 + (lane >> 2);
        int c0 = wn * 32 + (lane & 3) * 2;
        #pragma unroll
        for (int nf = 0; nf < 4; nf++) {
            sC[r0 * 68 + c0 + nf * 8]           = acc[nf][0];
            sC[r0 * 68 + c0 + nf * 8 + 1]       = acc[nf][1];
            sC[(r0 + 8) * 68 + c0 + nf * 8]     = acc[nf][2];
            sC[(r0 + 8) * 68 + c0 + nf * 8 + 1] = acc[nf][3];
        }
    }
    __syncthreads();

    // sign -> bits (sign(0)=+1 -> strict <0), pack one u64 word per batch row, compare
    if (t < 64) {
        ull word = 0;
        #pragma unroll
        for (int jj = 0; jj < 64; jj++)
            if (sC[t * 68 + jj] < 0.f) word |= 1ull << jj;
        int widx = n0 >> 6;
        ull old = g_est[p][(t * FF + f) * WD + widx];
        g_est[p ^ 1][(t * FF + f) * WD + widx] = word;
        unsigned msk = __ballot_sync(0xffffffffu, word != old);
        if (lane == 0 && msk) atomicAdd(&g_mismatch[iter], __popc(msk));
    }
}

// ---------------- final: cleanup argmax|sim|, est floats, iters/conv ----------------
__global__ void k_final(float* __restrict__ out, int out_size) {
    int b = blockIdx.x >> 2, f = blockIdx.x & 3;
    int t = threadIdx.x;
    const ull* Ef = g_est[NITER & 1];
    ull e[WD];
    #pragma unroll
    for (int w = 0; w < WD; w++) e[w] = Ef[(size_t)(b * FF + f) * WD + w];

    const ull* cb = g_cbD + (size_t)f * MM * WD;
    int bestA = -1, bestI = 0;
    for (int m = t; m < MM; m += 128) {
        const ull* rowp = cb + (size_t)m * WD;
        int h = 0;
        #pragma unroll
        for (int w = 0; w < WD; w++) h += __popcll(e[w] ^ rowp[w]);
        int s = DD - 2 * h;
        int a = s < 0 ? -s : s;
        if (a > bestA) { bestA = a; bestI = m; }
    }
    __shared__ int sAv[128], sIv[128];
    sAv[t] = bestA; sIv[t] = bestI;
    __syncthreads();
    for (int off = 64; off; off >>= 1) {
        if (t < off) {
            int a2 = sAv[t + off], i2 = sIv[t + off];
            if (a2 > sAv[t] || (a2 == sAv[t] && i2 < sIv[t])) { sAv[t] = a2; sIv[t] = i2; }
        }
        __syncthreads();
    }
    int idx = b * FF + f;
    if (t == 0 && idx < out_size) out[idx] = (float)sIv[0];

    if (out_size >= 256 + BB * FF * DD) {
        float* oe = out + 256 + (size_t)idx * DD;
        for (int d = t; d < DD; d += 128) {
            int bit = (int)((e[d >> 6] >> (d & 63)) & 1ULL);
            oe[d] = bit ? -1.f : 1.f;
        }
    }
    if (blockIdx.x == 0 && t == 0 && out_size >= 256 + BB * FF * DD + 2) {
        int iters = NITER, conv = 0;
        for (int tt = 0; tt < NITER; tt++)
            if (g_mismatch[tt] == 0) { iters = tt + 1; conv = 1; break; }
        out[256 + BB * FF * DD]     = (float)iters;
        out[256 + BB * FF * DD + 1] = (float)conv;
    }
}

// ---------------- launch ----------------
extern "C" void kernel_launch(void* const* d_in, const int* in_sizes, int n_in,
                              void* d_out, int out_size) {
    const float* input = nullptr;
    const float* est0  = nullptr;
    const float* cb    = nullptr;
    for (int i = 0; i < n_in; i++) {
        if (in_sizes[i] == BB * DD)            input = (const float*)d_in[i];
        else if (in_sizes[i] == BB * FF * DD)  est0  = (const float*)d_in[i];
        else if (in_sizes[i] == FF * MM * DD)  cb    = (const float*)d_in[i];
    }
    k_pack_est<<<80, 128>>>(input, est0);
    k_pack_cb<<<FF * MM / 4, 128>>>(cb);
    k_gram<<<FF * 36, 256>>>();
    for (int it = 0; it < NITER; it++)
        k_step<<<64, 256>>>(it);
    k_final<<<BB * FF, 128>>>((float*)d_out, out_size);
}

// round 3
// speedup vs baseline: 6.5276x; 1.0118x over previous
#include <cuda_runtime.h>
#include <cuda_fp16.h>
#include <cstdint>

typedef unsigned long long ull;

#define BB 64
#define FF 4
#define MM 4096
#define DD 1024
#define NITER 15
#define WD 16   // DD/64 sign-bit words

// ---------------- device scratch ----------------
__device__ ull g_est[2][BB * FF * WD];               // ping-pong estimate bits (1 = negative)
__device__ ull g_in[BB * WD];                        // input bits
__device__ ull g_cbD[FF * MM * WD];                  // codebook bits (for final cleanup)
__device__ __align__(16) __half g_cb16[(size_t)FF * MM * DD];  // codebook fp16
__device__ __align__(16) __half g_G[(size_t)FF * DD * DD];     // Gram: G[f] = C[f]^T C[f] (even ints, fp16-exact)
__device__ int g_mismatch[NITER];

// ---------------- helpers ----------------
__device__ __forceinline__ uint32_t smem_u32(const void* p) {
    return (uint32_t)__cvta_generic_to_shared(p);
}
__device__ __forceinline__ void ldm_x4(uint32_t& r0, uint32_t& r1, uint32_t& r2, uint32_t& r3, uint32_t addr) {
    asm volatile("ldmatrix.sync.aligned.m8n8.x4.shared.b16 {%0,%1,%2,%3}, [%4];\n"
                 : "=r"(r0), "=r"(r1), "=r"(r2), "=r"(r3) : "r"(addr));
}
__device__ __forceinline__ void ldm_x4_t(uint32_t& r0, uint32_t& r1, uint32_t& r2, uint32_t& r3, uint32_t addr) {
    asm volatile("ldmatrix.sync.aligned.m8n8.x4.trans.shared.b16 {%0,%1,%2,%3}, [%4];\n"
                 : "=r"(r0), "=r"(r1), "=r"(r2), "=r"(r3) : "r"(addr));
}
__device__ __forceinline__ void mma16816(float* c, uint32_t a0, uint32_t a1, uint32_t a2, uint32_t a3,
                                         uint32_t b0, uint32_t b1) {
    asm volatile("mma.sync.aligned.m16n8k16.row.col.f32.f16.f16.f32 "
                 "{%0,%1,%2,%3}, {%4,%5,%6,%7}, {%8,%9}, {%0,%1,%2,%3};\n"
                 : "+f"(c[0]), "+f"(c[1]), "+f"(c[2]), "+f"(c[3])
                 : "r"(a0), "r"(a1), "r"(a2), "r"(a3), "r"(b0), "r"(b1));
}

// ---------------- pack kernels ----------------
__global__ void k_pack_cb(const float* __restrict__ cb) {
    int row  = blockIdx.x * 4 + (threadIdx.x >> 5);
    int lane = threadIdx.x & 31;
    const float* src = cb + (size_t)row * DD;
    ull lo = 0;
    #pragma unroll
    for (int i = 0; i < 32; i++) {
        int d = i * 32 + lane;
        float v = src[d];
        g_cb16[(size_t)row * DD + d] = __float2half_rn(v);
        unsigned bal = __ballot_sync(0xffffffffu, v < 0.f);
        if ((i & 1) == 0) lo = bal;
        else if (lane == 0) g_cbD[row * WD + (i >> 1)] = lo | ((ull)bal << 32);
    }
}

__global__ void k_pack_est(const float* __restrict__ inp, const float* __restrict__ est0) {
    int row  = blockIdx.x * 4 + (threadIdx.x >> 5);
    int lane = threadIdx.x & 31;
    if (blockIdx.x == 0 && threadIdx.x < NITER) g_mismatch[threadIdx.x] = 0;
    const float* src;
    ull* dst;
    if (row < BB * FF) { src = est0 + (size_t)row * DD; dst = g_est[0] + row * WD; }
    else               { int b = row - BB * FF; src = inp + (size_t)b * DD; dst = g_in + b * WD; }
    ull lo = 0;
    #pragma unroll
    for (int i = 0; i < 32; i++) {
        unsigned bal = __ballot_sync(0xffffffffu, src[i * 32 + lane] < 0.f);
        if ((i & 1) == 0) lo = bal;
        else if (lane == 0) dst[i >> 1] = lo | ((ull)bal << 32);
    }
}

// ---------------- Gram matrix: G[f][d][d'] = sum_m C[m,d]*C[m,d'] ----------------
// grid = 4 * 36 upper-triangle 128x128 tiles. K = 4096, chunks of 32.
__global__ void k_gram() {
    int f = blockIdx.x / 36, pair = blockIdx.x % 36;
    int i = 0, rem = pair;
    while (rem >= 8 - i) { rem -= 8 - i; i++; }
    int j = i + rem;
    int gi = i << 7, gj = j << 7;
    int t = threadIdx.x, lane = t & 31, w = t >> 5;
    int wm = w >> 1, wn = w & 1;            // warp tile 32m x 64n

    __shared__ __align__(16) __half sI[2][32 * 128];
    __shared__ __align__(16) __half sJ[2][32 * 128];

    const __half* Cf = g_cb16 + (size_t)f * MM * DD;

    float acc[2][8][4];
    #pragma unroll
    for (int a = 0; a < 2; a++)
        #pragma unroll
        for (int b2 = 0; b2 < 8; b2++)
            #pragma unroll
            for (int q = 0; q < 4; q++) acc[a][b2][q] = 0.f;

    uint4 rI[2], rJ[2];
    #pragma unroll
    for (int q = 0; q < 2; q++) {
        int id = t * 2 + q, r = id >> 4, cc = id & 15;
        rI[q] = *(const uint4*)(Cf + (size_t)r * DD + gi + cc * 8);
        rJ[q] = *(const uint4*)(Cf + (size_t)r * DD + gj + cc * 8);
    }
    #pragma unroll
    for (int q = 0; q < 2; q++) {
        int id = t * 2 + q, r = id >> 4, cc = id & 15, sub = cc >> 3, c8 = cc & 7;
        *(uint4*)(&sI[0][sub * 2048 + r * 64 + ((c8 ^ (r & 7)) << 3)]) = rI[q];
        *(uint4*)(&sJ[0][sub * 2048 + r * 64 + ((c8 ^ (r & 7)) << 3)]) = rJ[q];
    }

    for (int c = 0; c < 128; c++) {
        if (c + 1 < 128) {
            int k0 = (c + 1) * 32;
            #pragma unroll
            for (int q = 0; q < 2; q++) {
                int id = t * 2 + q, r = id >> 4, cc = id & 15;
                rI[q] = *(const uint4*)(Cf + (size_t)(k0 + r) * DD + gi + cc * 8);
                rJ[q] = *(const uint4*)(Cf + (size_t)(k0 + r) * DD + gj + cc * 8);
            }
        }
        __syncthreads();
        const __half* bI = sI[c & 1];
        const __half* bJ = sJ[c & 1];
        #pragma unroll
        for (int k16 = 0; k16 < 2; k16++) {
            uint32_t a_[2][4];
            #pragma unroll
            for (int mi = 0; mi < 2; mi++) {
                int col = wm * 32 + mi * 16;
                int sub = col >> 6, cl = col & 63;
                int rr = k16 * 16 + (lane & 15);
                int cc8 = (cl >> 3) + (lane >> 4);
                ldm_x4_t(a_[mi][0], a_[mi][1], a_[mi][2], a_[mi][3],
                         smem_u32(bI + sub * 2048 + rr * 64 + ((cc8 ^ (rr & 7)) << 3)));
            }
            #pragma unroll
            for (int ni = 0; ni < 4; ni++) {
                int col = wn * 64 + ni * 16;
                int sub = col >> 6, cl = col & 63;
                int rr = k16 * 16 + (lane & 15);
                int cc8 = (cl >> 3) + (lane >> 4);
                uint32_t b0, b1, b2, b3;
                ldm_x4_t(b0, b1, b2, b3,
                         smem_u32(bJ + sub * 2048 + rr * 64 + ((cc8 ^ (rr & 7)) << 3)));
                #pragma unroll
                for (int mi = 0; mi < 2; mi++) {
                    // A via trans-ldmatrix: register order (r0, r2, r1, r3)
                    mma16816(acc[mi][ni * 2],     a_[mi][0], a_[mi][2], a_[mi][1], a_[mi][3], b0, b1);
                    mma16816(acc[mi][ni * 2 + 1], a_[mi][0], a_[mi][2], a_[mi][1], a_[mi][3], b2, b3);
                }
            }
        }
        if (c + 1 < 128) {
            int buf = (c + 1) & 1;
            #pragma unroll
            for (int q = 0; q < 2; q++) {
                int id = t * 2 + q, r = id >> 4, cc = id & 15, sub = cc >> 3, c8 = cc & 7;
                *(uint4*)(&sI[buf][sub * 2048 + r * 64 + ((c8 ^ (r & 7)) << 3)]) = rI[q];
                *(uint4*)(&sJ[buf][sub * 2048 + r * 64 + ((c8 ^ (r & 7)) << 3)]) = rJ[q];
            }
        }
    }

    __half* Gf = g_G + (size_t)f * DD * DD;
    #pragma unroll
    for (int mi = 0; mi < 2; mi++)
        #pragma unroll
        for (int nf = 0; nf < 8; nf++) {
            int row = gi + wm * 32 + mi * 16 + (lane >> 2);
            int col = gj + wn * 64 + nf * 8 + (lane & 3) * 2;
            float* cc = acc[mi][nf];
            *(__half2*)&Gf[(size_t)row * DD + col]       = __floats2half2_rn(cc[0], cc[1]);
            *(__half2*)&Gf[(size_t)(row + 8) * DD + col] = __floats2half2_rn(cc[2], cc[3]);
            if (i != j) {
                Gf[(size_t)col * DD + row]           = __float2half_rn(cc[0]);
                Gf[(size_t)(col + 1) * DD + row]     = __float2half_rn(cc[1]);
                Gf[(size_t)col * DD + row + 8]       = __float2half_rn(cc[2]);
                Gf[(size_t)(col + 1) * DD + row + 8] = __float2half_rn(cc[3]);
            }
        }
}

// ---------------- per-iteration: upd = sign(new_est @ G), fused sign/pack/converge ----------------
// grid = 4 factors * 16 n-tiles of 64. block 256 (8 warps, warp = 16m x 32n). K = 1024.
__global__ void k_step(int iter) {
    int f  = blockIdx.x >> 4;
    int n0 = (blockIdx.x & 15) << 6;
    int t = threadIdx.x, lane = t & 31, w = t >> 5;
    int wm = w >> 1, wn = w & 1;
    int p = iter & 1;

    __shared__ __align__(16) unsigned char raw[8192 + 16384 + 16384];
    ull*    sBits = (ull*)raw;                        // [64][16]
    __half* sA    = (__half*)(raw + 8192);            // [2][64*64]
    __half* sB    = (__half*)(raw + 8192 + 16384);    // [2][64*64]
    float*  sC    = (float*)raw;                      // alias, [64][68]

    // new_est bits: in ^ (xor of all est) ^ est_f
    const ull* E = g_est[p];
    for (int idx = t; idx < 1024; idx += 256) {
        int b = idx >> 4, wd = idx & 15;
        ull x = g_in[b * WD + wd];
        x ^= E[(b * FF + 0) * WD + wd] ^ E[(b * FF + 1) * WD + wd]
           ^ E[(b * FF + 2) * WD + wd] ^ E[(b * FF + 3) * WD + wd];
        sBits[idx] = x ^ E[(b * FF + f) * WD + wd];
    }

    const __half* Gf = g_G + (size_t)f * DD * DD + n0;
    uint4 rB[2];
    #pragma unroll
    for (int q = 0; q < 2; q++) {
        int id = t * 2 + q, r = id >> 3, c8 = id & 7;
        rB[q] = *(const uint4*)(Gf + (size_t)r * DD + c8 * 8);
    }
    __syncthreads();   // bits visible

    // STS chunk 0 (B) + gen A chunk 0
    #pragma unroll
    for (int q = 0; q < 2; q++) {
        int id = t * 2 + q, r = id >> 3, c8 = id & 7;
        int so = r * 64 + ((c8 ^ (r & 7)) << 3);
        *(uint4*)(&sB[so]) = rB[q];
        ull word = sBits[r * WD + 0];
        uint32_t u[4];
        #pragma unroll
        for (int jj = 0; jj < 4; jj++) {
            uint32_t b0 = (uint32_t)((word >> (c8 * 8 + jj * 2)) & 1ull);
            uint32_t b1 = (uint32_t)((word >> (c8 * 8 + jj * 2 + 1)) & 1ull);
            u[jj] = 0x3C003C00u | (b0 << 15) | (b1 << 31);
        }
        *(uint4*)(&sA[so]) = *(uint4*)u;
    }

    float acc[4][4];
    #pragma unroll
    for (int a = 0; a < 4; a++)
        #pragma unroll
        for (int q = 0; q < 4; q++) acc[a][q] = 0.f;

    for (int c = 0; c < 16; c++) {
        if (c + 1 < 16) {
            #pragma unroll
            for (int q = 0; q < 2; q++) {
                int id = t * 2 + q, r = id >> 3, c8 = id & 7;
                rB[q] = *(const uint4*)(Gf + (size_t)((c + 1) * 64 + r) * DD + c8 * 8);
            }
        }
        __syncthreads();
        const __half* bA = sA + (c & 1) * 4096;
        const __half* bB = sB + (c & 1) * 4096;
        #pragma unroll
        for (int k16 = 0; k16 < 4; k16++) {
            uint32_t a0, a1, a2, a3;
            int ar  = wm * 16 + (lane & 15);
            int ac8 = k16 * 2 + (lane >> 4);
            ldm_x4(a0, a1, a2, a3, smem_u32(bA + ar * 64 + ((ac8 ^ (ar & 7)) << 3)));
            #pragma unroll
            for (int ni = 0; ni < 2; ni++) {
                int br  = k16 * 16 + (lane & 15);
                int bc8 = wn * 4 + ni * 2 + (lane >> 4);
                uint32_t b0, b1, b2, b3;
                ldm_x4_t(b0, b1, b2, b3, smem_u32(bB + br * 64 + ((bc8 ^ (br & 7)) << 3)));
                mma16816(acc[ni * 2],     a0, a1, a2, a3, b0, b1);
                mma16816(acc[ni * 2 + 1], a0, a1, a2, a3, b2, b3);
            }
        }
        if (c + 1 < 16) {
            int buf = (c + 1) & 1;
            #pragma unroll
            for (int q = 0; q < 2; q++) {
                int id = t * 2 + q, r = id >> 3, c8 = id & 7;
                int so = buf * 4096 + r * 64 + ((c8 ^ (r & 7)) << 3);
                *(uint4*)(&sB[so]) = rB[q];
                ull word = sBits[r * WD + (c + 1)];
                uint32_t u[4];
                #pragma unroll
                for (int jj = 0; jj < 4; jj++) {
                    uint32_t b0 = (uint32_t)((word >> (c8 * 8 + jj * 2)) & 1ull);
                    uint32_t b1 = (uint32_t)((word >> (c8 * 8 + jj * 2 + 1)) & 1ull);
                    u[jj] = 0x3C003C00u | (b0 << 15) | (b1 << 31);
                }
                *(uint4*)(&sA[so]) = *(uint4*)u;
            }
        }
    }
    __syncthreads();

    // stage fp32 results
    {
        int r0 = wm * 16 + (lane >> 2);
        int c0 = wn * 32 + (lane & 3) * 2;
        #pragma unroll
        for (int nf = 0; nf < 4; nf++) {
            sC[r0 * 68 + c0 + nf * 8]           = acc[nf][0];
            sC[r0 * 68 + c0 + nf * 8 + 1]       = acc[nf][1];
            sC[(r0 + 8) * 68 + c0 + nf * 8]     = acc[nf][2];
            sC[(r0 + 8) * 68 + c0 + nf * 8 + 1] = acc[nf][3];
        }
    }
    __syncthreads();

    // sign -> bits (sign(0)=+1 -> strict <0), pack one u64 word per batch row, compare
    if (t < 64) {
        ull word = 0;
        #pragma unroll
        for (int jj = 0; jj < 64; jj++)
            if (sC[t * 68 + jj] < 0.f) word |= 1ull << jj;
        int widx = n0 >> 6;
        ull old = g_est[p][(t * FF + f) * WD + widx];
        g_est[p ^ 1][(t * FF + f) * WD + widx] = word;
        unsigned msk = __ballot_sync(0xffffffffu, word != old);
        if (lane == 0 && msk) atomicAdd(&g_mismatch[iter], __popc(msk));
    }
}

// ---------------- final: cleanup argmax|sim|, est floats, iters/conv ----------------
__global__ void k_final(float* __restrict__ out, int out_size) {
    int b = blockIdx.x >> 2, f = blockIdx.x & 3;
    int t = threadIdx.x;
    const ull* Ef = g_est[NITER & 1];
    ull e[WD];
    #pragma unroll
    for (int w = 0; w < WD; w++) e[w] = Ef[(size_t)(b * FF + f) * WD + w];

    const ull* cb = g_cbD + (size_t)f * MM * WD;
    int bestA = -1, bestI = 0;
    for (int m = t; m < MM; m += 128) {
        const ull* rowp = cb + (size_t)m * WD;
        int h = 0;
        #pragma unroll
        for (int w = 0; w < WD; w++) h += __popcll(e[w] ^ rowp[w]);
        int s = DD - 2 * h;
        int a = s < 0 ? -s : s;
        if (a > bestA) { bestA = a; bestI = m; }
    }
    __shared__ int sAv[128], sIv[128];
    sAv[t] = bestA; sIv[t] = bestI;
    __syncthreads();
    for (int off = 64; off; off >>= 1) {
        if (t < off) {
            int a2 = sAv[t + off], i2 = sIv[t + off];
            if (a2 > sAv[t] || (a2 == sAv[t] && i2 < sIv[t])) { sAv[t] = a2; sIv[t] = i2; }
        }
        __syncthreads();
    }
    int idx = b * FF + f;
    if (t == 0 && idx < out_size) out[idx] = (float)sIv[0];

    if (out_size >= 256 + BB * FF * DD) {
        float* oe = out + 256 + (size_t)idx * DD;
        for (int d = t; d < DD; d += 128) {
            int bit = (int)((e[d >> 6] >> (d & 63)) & 1ULL);
            oe[d] = bit ? -1.f : 1.f;
        }
    }
    if (blockIdx.x == 0 && t == 0 && out_size >= 256 + BB * FF * DD + 2) {
        int iters = NITER, conv = 0;
        for (int tt = 0; tt < NITER; tt++)
            if (g_mismatch[tt] == 0) { iters = tt + 1; conv = 1; break; }
        out[256 + BB * FF * DD]     = (float)iters;
        out[256 + BB * FF * DD + 1] = (float)conv;
    }
}

// ---------------- launch ----------------
extern "C" void kernel_launch(void* const* d_in, const int* in_sizes, int n_in,
                              void* d_out, int out_size) {
    const float* input = nullptr;
    const float* est0  = nullptr;
    const float* cb    = nullptr;
    for (int i = 0; i < n_in; i++) {
        if (in_sizes[i] == BB * DD)            input = (const float*)d_in[i];
        else if (in_sizes[i] == BB * FF * DD)  est0  = (const float*)d_in[i];
        else if (in_sizes[i] == FF * MM * DD)  cb    = (const float*)d_in[i];
    }
    k_pack_est<<<80, 128>>>(input, est0);
    k_pack_cb<<<FF * MM / 4, 128>>>(cb);
    k_gram<<<FF * 36, 256>>>();
    for (int it = 0; it < NITER; it++)
        k_step<<<64, 256>>>(it);
    k_final<<<BB * FF, 128>>>((float*)d_out, out_size);
}

// round 4
// speedup vs baseline: 7.7453x; 1.1866x over previous
#include <cuda_runtime.h>
#include <cuda_fp16.h>
#include <cstdint>

typedef unsigned long long ull;

#define BB 64
#define FF 4
#define MM 4096
#define DD 1024
#define NITER 15
#define WD 16   // DD/64 sign-bit words
#define GRID_RUN 64

// ---------------- device scratch ----------------
__device__ ull g_est[2][BB * FF * WD];               // ping-pong estimate bits (1 = negative)
__device__ ull g_in[BB * WD];                        // input bits
__device__ ull g_cbD[FF * MM * WD];                  // codebook bits (for final cleanup)
__device__ __align__(16) __half g_cb16[(size_t)FF * MM * DD];  // codebook fp16
__device__ __align__(16) __half g_G[(size_t)FF * DD * DD];     // Gram: G[f] = C[f]^T C[f]
__device__ int g_mismatch[NITER];
__device__ int g_bar[NITER];

// ---------------- helpers ----------------
__device__ __forceinline__ uint32_t smem_u32(const void* p) {
    return (uint32_t)__cvta_generic_to_shared(p);
}
__device__ __forceinline__ void ldm_x4(uint32_t& r0, uint32_t& r1, uint32_t& r2, uint32_t& r3, uint32_t addr) {
    asm volatile("ldmatrix.sync.aligned.m8n8.x4.shared.b16 {%0,%1,%2,%3}, [%4];\n"
                 : "=r"(r0), "=r"(r1), "=r"(r2), "=r"(r3) : "r"(addr));
}
__device__ __forceinline__ void ldm_x4_t(uint32_t& r0, uint32_t& r1, uint32_t& r2, uint32_t& r3, uint32_t addr) {
    asm volatile("ldmatrix.sync.aligned.m8n8.x4.trans.shared.b16 {%0,%1,%2,%3}, [%4];\n"
                 : "=r"(r0), "=r"(r1), "=r"(r2), "=r"(r3) : "r"(addr));
}
__device__ __forceinline__ void mma16816(float* c, uint32_t a0, uint32_t a1, uint32_t a2, uint32_t a3,
                                         uint32_t b0, uint32_t b1) {
    asm volatile("mma.sync.aligned.m16n8k16.row.col.f32.f16.f16.f32 "
                 "{%0,%1,%2,%3}, {%4,%5,%6,%7}, {%8,%9}, {%0,%1,%2,%3};\n"
                 : "+f"(c[0]), "+f"(c[1]), "+f"(c[2]), "+f"(c[3])
                 : "r"(a0), "r"(a1), "r"(a2), "r"(a3), "r"(b0), "r"(b1));
}

// grid barrier: all 64 CTAs co-resident (grid 64 <= 148 SMs)
__device__ __forceinline__ void grid_bar(int it) {
    __syncthreads();
    if (threadIdx.x == 0) {
        asm volatile("red.release.gpu.global.add.u32 [%0], %1;"
                     :: "l"(g_bar + it), "r"(1u) : "memory");
        unsigned v;
        do {
            asm volatile("ld.acquire.gpu.global.u32 %0, [%1];"
                         : "=r"(v) : "l"(g_bar + it) : "memory");
        } while (v < GRID_RUN);
    }
    __syncthreads();
}

// ---------------- pack kernels ----------------
__global__ void k_pack_cb(const float* __restrict__ cb) {
    int row  = blockIdx.x * 4 + (threadIdx.x >> 5);
    int lane = threadIdx.x & 31;
    const float* src = cb + (size_t)row * DD;
    ull lo = 0;
    #pragma unroll
    for (int i = 0; i < 32; i++) {
        int d = i * 32 + lane;
        float v = src[d];
        g_cb16[(size_t)row * DD + d] = __float2half_rn(v);
        unsigned bal = __ballot_sync(0xffffffffu, v < 0.f);
        if ((i & 1) == 0) lo = bal;
        else if (lane == 0) g_cbD[row * WD + (i >> 1)] = lo | ((ull)bal << 32);
    }
}

__global__ void k_pack_est(const float* __restrict__ inp, const float* __restrict__ est0) {
    int row  = blockIdx.x * 4 + (threadIdx.x >> 5);
    int lane = threadIdx.x & 31;
    if (blockIdx.x == 0 && threadIdx.x < NITER) {
        g_mismatch[threadIdx.x] = 0;
        g_bar[threadIdx.x] = 0;
    }
    const float* src;
    ull* dst;
    if (row < BB * FF) { src = est0 + (size_t)row * DD; dst = g_est[0] + row * WD; }
    else               { int b = row - BB * FF; src = inp + (size_t)b * DD; dst = g_in + b * WD; }
    ull lo = 0;
    #pragma unroll
    for (int i = 0; i < 32; i++) {
        unsigned bal = __ballot_sync(0xffffffffu, src[i * 32 + lane] < 0.f);
        if ((i & 1) == 0) lo = bal;
        else if (lane == 0) dst[i >> 1] = lo | ((ull)bal << 32);
    }
}

// ---------------- Gram matrix: G[f][d][d'] = sum_m C[m,d]*C[m,d'] ----------------
__global__ void k_gram() {
    int f = blockIdx.x / 36, pair = blockIdx.x % 36;
    int i = 0, rem = pair;
    while (rem >= 8 - i) { rem -= 8 - i; i++; }
    int j = i + rem;
    int gi = i << 7, gj = j << 7;
    int t = threadIdx.x, lane = t & 31, w = t >> 5;
    int wm = w >> 1, wn = w & 1;            // warp tile 32m x 64n

    __shared__ __align__(16) __half sI[2][32 * 128];
    __shared__ __align__(16) __half sJ[2][32 * 128];

    const __half* Cf = g_cb16 + (size_t)f * MM * DD;

    float acc[2][8][4];
    #pragma unroll
    for (int a = 0; a < 2; a++)
        #pragma unroll
        for (int b2 = 0; b2 < 8; b2++)
            #pragma unroll
            for (int q = 0; q < 4; q++) acc[a][b2][q] = 0.f;

    uint4 rI[2], rJ[2];
    #pragma unroll
    for (int q = 0; q < 2; q++) {
        int id = t * 2 + q, r = id >> 4, cc = id & 15;
        rI[q] = *(const uint4*)(Cf + (size_t)r * DD + gi + cc * 8);
        rJ[q] = *(const uint4*)(Cf + (size_t)r * DD + gj + cc * 8);
    }
    #pragma unroll
    for (int q = 0; q < 2; q++) {
        int id = t * 2 + q, r = id >> 4, cc = id & 15, sub = cc >> 3, c8 = cc & 7;
        *(uint4*)(&sI[0][sub * 2048 + r * 64 + ((c8 ^ (r & 7)) << 3)]) = rI[q];
        *(uint4*)(&sJ[0][sub * 2048 + r * 64 + ((c8 ^ (r & 7)) << 3)]) = rJ[q];
    }

    for (int c = 0; c < 128; c++) {
        if (c + 1 < 128) {
            int k0 = (c + 1) * 32;
            #pragma unroll
            for (int q = 0; q < 2; q++) {
                int id = t * 2 + q, r = id >> 4, cc = id & 15;
                rI[q] = *(const uint4*)(Cf + (size_t)(k0 + r) * DD + gi + cc * 8);
                rJ[q] = *(const uint4*)(Cf + (size_t)(k0 + r) * DD + gj + cc * 8);
            }
        }
        __syncthreads();
        const __half* bI = sI[c & 1];
        const __half* bJ = sJ[c & 1];
        #pragma unroll
        for (int k16 = 0; k16 < 2; k16++) {
            uint32_t a_[2][4];
            #pragma unroll
            for (int mi = 0; mi < 2; mi++) {
                int col = wm * 32 + mi * 16;
                int sub = col >> 6, cl = col & 63;
                int rr = k16 * 16 + (lane & 15);
                int cc8 = (cl >> 3) + (lane >> 4);
                ldm_x4_t(a_[mi][0], a_[mi][1], a_[mi][2], a_[mi][3],
                         smem_u32(bI + sub * 2048 + rr * 64 + ((cc8 ^ (rr & 7)) << 3)));
            }
            #pragma unroll
            for (int ni = 0; ni < 4; ni++) {
                int col = wn * 64 + ni * 16;
                int sub = col >> 6, cl = col & 63;
                int rr = k16 * 16 + (lane & 15);
                int cc8 = (cl >> 3) + (lane >> 4);
                uint32_t b0, b1, b2, b3;
                ldm_x4_t(b0, b1, b2, b3,
                         smem_u32(bJ + sub * 2048 + rr * 64 + ((cc8 ^ (rr & 7)) << 3)));
                #pragma unroll
                for (int mi = 0; mi < 2; mi++) {
                    mma16816(acc[mi][ni * 2],     a_[mi][0], a_[mi][2], a_[mi][1], a_[mi][3], b0, b1);
                    mma16816(acc[mi][ni * 2 + 1], a_[mi][0], a_[mi][2], a_[mi][1], a_[mi][3], b2, b3);
                }
            }
        }
        if (c + 1 < 128) {
            int buf = (c + 1) & 1;
            #pragma unroll
            for (int q = 0; q < 2; q++) {
                int id = t * 2 + q, r = id >> 4, cc = id & 15, sub = cc >> 3, c8 = cc & 7;
                *(uint4*)(&sI[buf][sub * 2048 + r * 64 + ((c8 ^ (r & 7)) << 3)]) = rI[q];
                *(uint4*)(&sJ[buf][sub * 2048 + r * 64 + ((c8 ^ (r & 7)) << 3)]) = rJ[q];
            }
        }
    }

    __half* Gf = g_G + (size_t)f * DD * DD;
    #pragma unroll
    for (int mi = 0; mi < 2; mi++)
        #pragma unroll
        for (int nf = 0; nf < 8; nf++) {
            int row = gi + wm * 32 + mi * 16 + (lane >> 2);
            int col = gj + wn * 64 + nf * 8 + (lane & 3) * 2;
            float* cc = acc[mi][nf];
            *(__half2*)&Gf[(size_t)row * DD + col]       = __floats2half2_rn(cc[0], cc[1]);
            *(__half2*)&Gf[(size_t)(row + 8) * DD + col] = __floats2half2_rn(cc[2], cc[3]);
            if (i != j) {
                Gf[(size_t)col * DD + row]           = __float2half_rn(cc[0]);
                Gf[(size_t)(col + 1) * DD + row]     = __float2half_rn(cc[1]);
                Gf[(size_t)col * DD + row + 8]       = __float2half_rn(cc[2]);
                Gf[(size_t)(col + 1) * DD + row + 8] = __float2half_rn(cc[3]);
            }
        }
}

// ---------------- A expansion: bits -> fp16 +-1, one 64x64 chunk, swizzled ----------------
__device__ __forceinline__ void expandA(__half* sA, const ull* sBits, int c, int buf, int t) {
    #pragma unroll
    for (int q = 0; q < 2; q++) {
        int id = t * 2 + q, r = id >> 3, c8 = id & 7;
        uint32_t bb = (uint32_t)(sBits[r * WD + c] >> (c8 * 8)) & 0xFFu;
        uint32_t u[4];
        #pragma unroll
        for (int jj = 0; jj < 4; jj++) {
            u[jj] = 0x3C003C00u | ((bb & 1u) << 15) | ((bb & 2u) << 30);
            bb >>= 2;
        }
        *(uint4*)(&sA[buf * 4096 + r * 64 + ((c8 ^ (r & 7)) << 3)]) = *(uint4*)u;
    }
}

// ---------------- persistent kernel: 15 iterations + cleanup ----------------
// grid = 64 CTAs: f = blockIdx>>4, n0 = (blockIdx&15)*64. 256 threads (8 warps, 16m x 32n each).
// smem: sG 128KB resident G slice | sA 2x8KB double-buffered A chunks | aux 17.4KB (sBits / sC / cleanup)
__global__ void __launch_bounds__(256) k_run(float* __restrict__ out, int out_size) {
    extern __shared__ __align__(16) char smem[];
    __half* sG    = (__half*)smem;
    __half* sA    = (__half*)(smem + 131072);
    char*   aux   = smem + 147456;
    ull*    sBits = (ull*)aux;           // 8 KB
    float*  sC    = (float*)aux;         // 64 x 68 floats = 17408 B

    int t = threadIdx.x, lane = t & 31, w = t >> 5;
    int wm = w >> 1, wn = w & 1;
    int f  = blockIdx.x >> 4;
    int n0 = (blockIdx.x & 15) << 6;

    // load resident G slice (1024 rows x 64 cols), swizzled for ldmatrix
    {
        const __half* Gf = g_G + (size_t)f * DD * DD + n0;
        for (int idx = t; idx < 8192; idx += 256) {
            int r = idx >> 3, c8 = idx & 7;
            uint4 v = *(const uint4*)(Gf + (size_t)r * DD + c8 * 8);
            *(uint4*)(&sG[r * 64 + ((c8 ^ (r & 7)) << 3)]) = v;
        }
    }

    for (int it = 0; it < NITER; it++) {
        int p = it & 1;
        const ull* E = g_est[p];
        __syncthreads();   // aux free (previous epilogue / G load done)

        // new_est bits: in ^ (xor of all est) ^ est_f
        for (int idx = t; idx < BB * WD; idx += 256) {
            int b = idx >> 4, wd = idx & 15;
            ull x = g_in[b * WD + wd];
            x ^= E[(b * FF + 0) * WD + wd] ^ E[(b * FF + 1) * WD + wd]
               ^ E[(b * FF + 2) * WD + wd] ^ E[(b * FF + 3) * WD + wd];
            sBits[idx] = x ^ E[(b * FF + f) * WD + wd];
        }
        __syncthreads();

        expandA(sA, sBits, 0, 0, t);
        __syncthreads();

        float acc[4][4];
        #pragma unroll
        for (int a = 0; a < 4; a++)
            #pragma unroll
            for (int q = 0; q < 4; q++) acc[a][q] = 0.f;

        for (int c = 0; c < 16; c++) {
            int cur = c & 1;
            if (c + 1 < 16) expandA(sA, sBits, c + 1, cur ^ 1, t);
            const __half* bA = sA + cur * 4096;
            #pragma unroll
            for (int k16 = 0; k16 < 4; k16++) {
                uint32_t a0, a1, a2, a3;
                int ar  = wm * 16 + (lane & 15);
                int ac8 = k16 * 2 + (lane >> 4);
                ldm_x4(a0, a1, a2, a3, smem_u32(bA + ar * 64 + ((ac8 ^ (ar & 7)) << 3)));
                #pragma unroll
                for (int ni = 0; ni < 2; ni++) {
                    int br  = c * 64 + k16 * 16 + (lane & 15);
                    int bc8 = wn * 4 + ni * 2 + (lane >> 4);
                    uint32_t b0, b1, b2, b3;
                    ldm_x4_t(b0, b1, b2, b3, smem_u32(sG + br * 64 + ((bc8 ^ (br & 7)) << 3)));
                    mma16816(acc[ni * 2],     a0, a1, a2, a3, b0, b1);
                    mma16816(acc[ni * 2 + 1], a0, a1, a2, a3, b2, b3);
                }
            }
            __syncthreads();
        }

        // stage fp32 results (aux reused: sBits dead now)
        {
            int r0 = wm * 16 + (lane >> 2);
            int c0 = wn * 32 + (lane & 3) * 2;
            #pragma unroll
            for (int nf = 0; nf < 4; nf++) {
                sC[r0 * 68 + c0 + nf * 8]           = acc[nf][0];
                sC[r0 * 68 + c0 + nf * 8 + 1]       = acc[nf][1];
                sC[(r0 + 8) * 68 + c0 + nf * 8]     = acc[nf][2];
                sC[(r0 + 8) * 68 + c0 + nf * 8 + 1] = acc[nf][3];
            }
        }
        __syncthreads();

        // sign -> bits (sign(0)=+1 -> strict <0), pack, compare
        if (t < 64) {
            ull word = 0;
            #pragma unroll
            for (int jj = 0; jj < 64; jj++)
                if (sC[t * 68 + jj] < 0.f) word |= 1ull << jj;
            int widx = n0 >> 6;
            ull old = g_est[p][(t * FF + f) * WD + widx];
            g_est[p ^ 1][(t * FF + f) * WD + widx] = word;
            unsigned msk = __ballot_sync(0xffffffffu, word != old);
            if (lane == 0 && msk) atomicAdd(&g_mismatch[it], __popc(msk));
        }

        grid_bar(it);
    }

    // ---------------- cleanup: argmax|sim|, est floats, iters/conv ----------------
    // remap so each CTA touches one codebook: f2 = blockIdx>>4, 4 batches bgrp*4..+3
    {
        int f2 = blockIdx.x >> 4;
        int bgrp = blockIdx.x & 15;
        ull* sE = (ull*)aux;                       // 4 x 16 ull = 512 B
        int* rA = (int*)(aux + 512);               // 256 ints
        int* rI = (int*)(aux + 1536);              // 256 ints
        const ull* Ef = g_est[NITER & 1];

        if (t < 64) {
            int j = t >> 4, wd = t & 15;
            sE[j * WD + wd] = Ef[(size_t)((bgrp * 4 + j) * FF + f2) * WD + wd];
        }
        __syncthreads();

        const ull* cb = g_cbD + (size_t)f2 * MM * WD;
        int bestA[4] = {-1, -1, -1, -1}, bestI[4] = {0, 0, 0, 0};
        for (int m = t; m < MM; m += 256) {
            ull rb[WD];
            const ull* rp = cb + (size_t)m * WD;
            #pragma unroll
            for (int q = 0; q < WD; q++) rb[q] = rp[q];
            #pragma unroll
            for (int j = 0; j < 4; j++) {
                int h = 0;
                #pragma unroll
                for (int q = 0; q < WD; q++) h += __popcll(rb[q] ^ sE[j * WD + q]);
                int s = DD - 2 * h;
                int a = s < 0 ? -s : s;
                if (a > bestA[j]) { bestA[j] = a; bestI[j] = m; }
            }
        }

        #pragma unroll
        for (int j = 0; j < 4; j++) {
            __syncthreads();
            rA[t] = bestA[j]; rI[t] = bestI[j];
            __syncthreads();
            for (int off = 128; off; off >>= 1) {
                if (t < off) {
                    int a2 = rA[t + off], i2 = rI[t + off];
                    if (a2 > rA[t] || (a2 == rA[t] && i2 < rI[t])) { rA[t] = a2; rI[t] = i2; }
                }
                __syncthreads();
            }
            int idx = (bgrp * 4 + j) * FF + f2;
            if (t == 0 && idx < out_size) out[idx] = (float)rI[0];
            if (out_size >= 256 + BB * FF * DD) {
                float* oe = out + 256 + (size_t)idx * DD;
                for (int d = t; d < DD; d += 256) {
                    int bit = (int)((sE[j * WD + (d >> 6)] >> (d & 63)) & 1ULL);
                    oe[d] = bit ? -1.f : 1.f;
                }
            }
        }

        if (blockIdx.x == 0 && t == 0 && out_size >= 256 + BB * FF * DD + 2) {
            int iters = NITER, conv = 0;
            for (int tt = 0; tt < NITER; tt++)
                if (g_mismatch[tt] == 0) { iters = tt + 1; conv = 1; break; }
            out[256 + BB * FF * DD]     = (float)iters;
            out[256 + BB * FF * DD + 1] = (float)conv;
        }
    }
}

// ---------------- launch ----------------
extern "C" void kernel_launch(void* const* d_in, const int* in_sizes, int n_in,
                              void* d_out, int out_size) {
    const float* input = nullptr;
    const float* est0  = nullptr;
    const float* cb    = nullptr;
    for (int i = 0; i < n_in; i++) {
        if (in_sizes[i] == BB * DD)            input = (const float*)d_in[i];
        else if (in_sizes[i] == BB * FF * DD)  est0  = (const float*)d_in[i];
        else if (in_sizes[i] == FF * MM * DD)  cb    = (const float*)d_in[i];
    }
    static bool attr_set = false;
    if (!attr_set) {
        cudaFuncSetAttribute(k_run, cudaFuncAttributeMaxDynamicSharedMemorySize, 164864);
        attr_set = true;
    }
    k_pack_est<<<80, 128>>>(input, est0);
    k_pack_cb<<<FF * MM / 4, 128>>>(cb);
    k_gram<<<FF * 36, 256>>>();
    k_run<<<GRID_RUN, 256, 164864>>>((float*)d_out, out_size);
}

// round 5
// speedup vs baseline: 9.2816x; 1.1983x over previous
#include <cuda_runtime.h>
#include <cuda_fp16.h>
#include <cstdint>

typedef unsigned long long ull;

#define BB 64
#define FF 4
#define MM 4096
#define DD 1024
#define NITER 15
#define WD 16            // DD/64 sign-bit words (u64)
#define GRID_RUN 128

// ---------------- device scratch ----------------
__device__ ull g_est[2][BB * FF * WD];               // ping-pong estimate bits (1 = negative)
__device__ ull g_in[BB * WD];                        // input bits
__device__ ull g_cbD[FF * MM * WD];                  // codebook bits (cleanup)
__device__ __align__(16) __half g_cb16[(size_t)FF * MM * DD];  // codebook fp16
__device__ __align__(16) __half g_G[(size_t)FF * DD * DD];     // Gram: G[f] = C[f]^T C[f]
__device__ int g_mismatch[NITER];
__device__ int g_bar[NITER];

// ---------------- helpers ----------------
__device__ __forceinline__ uint32_t smem_u32(const void* p) {
    return (uint32_t)__cvta_generic_to_shared(p);
}
__device__ __forceinline__ void ldm_x4_t(uint32_t& r0, uint32_t& r1, uint32_t& r2, uint32_t& r3, uint32_t addr) {
    asm volatile("ldmatrix.sync.aligned.m8n8.x4.trans.shared.b16 {%0,%1,%2,%3}, [%4];\n"
                 : "=r"(r0), "=r"(r1), "=r"(r2), "=r"(r3) : "r"(addr));
}
__device__ __forceinline__ void mma16816(float* c, uint32_t a0, uint32_t a1, uint32_t a2, uint32_t a3,
                                         uint32_t b0, uint32_t b1) {
    asm volatile("mma.sync.aligned.m16n8k16.row.col.f32.f16.f16.f32 "
                 "{%0,%1,%2,%3}, {%4,%5,%6,%7}, {%8,%9}, {%0,%1,%2,%3};\n"
                 : "+f"(c[0]), "+f"(c[1]), "+f"(c[2]), "+f"(c[3])
                 : "r"(a0), "r"(a1), "r"(a2), "r"(a3), "r"(b0), "r"(b1));
}
// 2 sign bits -> packed half2 of +-1 (bit=1 -> -1)
__device__ __forceinline__ uint32_t bexp(uint32_t t) {
    return 0x3C003C00u | ((t & 1u) << 15) | ((t & 2u) << 30);
}
// spread 16 bits to every 4th bit of a u64
__device__ __forceinline__ ull spr4(uint32_t x) {
    ull v = x & 0xFFFFull;
    v = (v | v << 24) & 0x000000FF000000FFull;
    v = (v | v << 12) & 0x000F000F000F000Full;
    v = (v | v << 6)  & 0x0303030303030303ull;
    v = (v | v << 3)  & 0x1111111111111111ull;
    return v;
}

// grid barrier: all GRID_RUN CTAs co-resident
__device__ __forceinline__ void grid_bar(int it) {
    __syncthreads();
    if (threadIdx.x == 0) {
        asm volatile("red.release.gpu.global.add.u32 [%0], %1;"
                     :: "l"(g_bar + it), "r"(1u) : "memory");
        unsigned v;
        do {
            asm volatile("ld.acquire.gpu.global.u32 %0, [%1];"
                         : "=r"(v) : "l"(g_bar + it) : "memory");
        } while (v < GRID_RUN);
    }
    __syncthreads();
}

// ---------------- pack kernels ----------------
// warp per codebook row: float4 loads, half2 stores, ballot+spread bit pack
__global__ void k_pack_cb(const float* __restrict__ cb) {
    int row  = blockIdx.x * 4 + (threadIdx.x >> 5);
    int lane = threadIdx.x & 31;
    const float* src = cb + (size_t)row * DD;
    __half* dsth = g_cb16 + (size_t)row * DD;
    ull* dstb = g_cbD + row * WD;
    #pragma unroll
    for (int i = 0; i < 8; i++) {
        int d = i * 128 + lane * 4;
        float4 v = *(const float4*)(src + d);
        __half2 h0 = __floats2half2_rn(v.x, v.y);
        __half2 h1 = __floats2half2_rn(v.z, v.w);
        uint2 st;
        st.x = *reinterpret_cast<unsigned*>(&h0);
        st.y = *reinterpret_cast<unsigned*>(&h1);
        *(uint2*)(dsth + d) = st;
        unsigned b0 = __ballot_sync(0xffffffffu, v.x < 0.f);
        unsigned b1 = __ballot_sync(0xffffffffu, v.y < 0.f);
        unsigned b2 = __ballot_sync(0xffffffffu, v.z < 0.f);
        unsigned b3 = __ballot_sync(0xffffffffu, v.w < 0.f);
        if (lane == 0) {
            dstb[i * 2]     = spr4(b0) | (spr4(b1) << 1) | (spr4(b2) << 2) | (spr4(b3) << 3);
            dstb[i * 2 + 1] = spr4(b0 >> 16) | (spr4(b1 >> 16) << 1) | (spr4(b2 >> 16) << 2) | (spr4(b3 >> 16) << 3);
        }
    }
}

__global__ void k_pack_est(const float* __restrict__ inp, const float* __restrict__ est0) {
    int row  = blockIdx.x * 4 + (threadIdx.x >> 5);
    int lane = threadIdx.x & 31;
    if (blockIdx.x == 0 && threadIdx.x < NITER) {
        g_mismatch[threadIdx.x] = 0;
        g_bar[threadIdx.x] = 0;
    }
    const float* src;
    ull* dst;
    if (row < BB * FF) { src = est0 + (size_t)row * DD; dst = g_est[0] + row * WD; }
    else               { int b = row - BB * FF; src = inp + (size_t)b * DD; dst = g_in + b * WD; }
    ull lo = 0;
    #pragma unroll
    for (int i = 0; i < 32; i++) {
        unsigned bal = __ballot_sync(0xffffffffu, src[i * 32 + lane] < 0.f);
        if ((i & 1) == 0) lo = bal;
        else if (lane == 0) dst[i >> 1] = lo | ((ull)bal << 32);
    }
}

// ---------------- Gram matrix: G[f][d][d'] = sum_m C[m,d]*C[m,d'] ----------------
__global__ void k_gram() {
    int f = blockIdx.x / 36, pair = blockIdx.x % 36;
    int i = 0, rem = pair;
    while (rem >= 8 - i) { rem -= 8 - i; i++; }
    int j = i + rem;
    int gi = i << 7, gj = j << 7;
    int t = threadIdx.x, lane = t & 31, w = t >> 5;
    int wm = w >> 1, wn = w & 1;            // warp tile 32m x 64n

    __shared__ __align__(16) __half sI[2][32 * 128];
    __shared__ __align__(16) __half sJ[2][32 * 128];

    const __half* Cf = g_cb16 + (size_t)f * MM * DD;

    float acc[2][8][4];
    #pragma unroll
    for (int a = 0; a < 2; a++)
        #pragma unroll
        for (int b2 = 0; b2 < 8; b2++)
            #pragma unroll
            for (int q = 0; q < 4; q++) acc[a][b2][q] = 0.f;

    uint4 rI[2], rJ[2];
    #pragma unroll
    for (int q = 0; q < 2; q++) {
        int id = t * 2 + q, r = id >> 4, cc = id & 15;
        rI[q] = *(const uint4*)(Cf + (size_t)r * DD + gi + cc * 8);
        rJ[q] = *(const uint4*)(Cf + (size_t)r * DD + gj + cc * 8);
    }
    #pragma unroll
    for (int q = 0; q < 2; q++) {
        int id = t * 2 + q, r = id >> 4, cc = id & 15, sub = cc >> 3, c8 = cc & 7;
        *(uint4*)(&sI[0][sub * 2048 + r * 64 + ((c8 ^ (r & 7)) << 3)]) = rI[q];
        *(uint4*)(&sJ[0][sub * 2048 + r * 64 + ((c8 ^ (r & 7)) << 3)]) = rJ[q];
    }

    for (int c = 0; c < 128; c++) {
        if (c + 1 < 128) {
            int k0 = (c + 1) * 32;
            #pragma unroll
            for (int q = 0; q < 2; q++) {
                int id = t * 2 + q, r = id >> 4, cc = id & 15;
                rI[q] = *(const uint4*)(Cf + (size_t)(k0 + r) * DD + gi + cc * 8);
                rJ[q] = *(const uint4*)(Cf + (size_t)(k0 + r) * DD + gj + cc * 8);
            }
        }
        __syncthreads();
        const __half* bI = sI[c & 1];
        const __half* bJ = sJ[c & 1];
        #pragma unroll
        for (int k16 = 0; k16 < 2; k16++) {
            uint32_t a_[2][4];
            #pragma unroll
            for (int mi = 0; mi < 2; mi++) {
                int col = wm * 32 + mi * 16;
                int sub = col >> 6, cl = col & 63;
                int rr = k16 * 16 + (lane & 15);
                int cc8 = (cl >> 3) + (lane >> 4);
                ldm_x4_t(a_[mi][0], a_[mi][1], a_[mi][2], a_[mi][3],
                         smem_u32(bI + sub * 2048 + rr * 64 + ((cc8 ^ (rr & 7)) << 3)));
            }
            #pragma unroll
            for (int ni = 0; ni < 4; ni++) {
                int col = wn * 64 + ni * 16;
                int sub = col >> 6, cl = col & 63;
                int rr = k16 * 16 + (lane & 15);
                int cc8 = (cl >> 3) + (lane >> 4);
                uint32_t b0, b1, b2, b3;
                ldm_x4_t(b0, b1, b2, b3,
                         smem_u32(bJ + sub * 2048 + rr * 64 + ((cc8 ^ (rr & 7)) << 3)));
                #pragma unroll
                for (int mi = 0; mi < 2; mi++) {
                    mma16816(acc[mi][ni * 2],     a_[mi][0], a_[mi][2], a_[mi][1], a_[mi][3], b0, b1);
                    mma16816(acc[mi][ni * 2 + 1], a_[mi][0], a_[mi][2], a_[mi][1], a_[mi][3], b2, b3);
                }
            }
        }
        if (c + 1 < 128) {
            int buf = (c + 1) & 1;
            #pragma unroll
            for (int q = 0; q < 2; q++) {
                int id = t * 2 + q, r = id >> 4, cc = id & 15, sub = cc >> 3, c8 = cc & 7;
                *(uint4*)(&sI[buf][sub * 2048 + r * 64 + ((c8 ^ (r & 7)) << 3)]) = rI[q];
                *(uint4*)(&sJ[buf][sub * 2048 + r * 64 + ((c8 ^ (r & 7)) << 3)]) = rJ[q];
            }
        }
    }

    __half* Gf = g_G + (size_t)f * DD * DD;
    #pragma unroll
    for (int mi = 0; mi < 2; mi++)
        #pragma unroll
        for (int nf = 0; nf < 8; nf++) {
            int row = gi + wm * 32 + mi * 16 + (lane >> 2);
            int col = gj + wn * 64 + nf * 8 + (lane & 3) * 2;
            float* cc = acc[mi][nf];
            *(__half2*)&Gf[(size_t)row * DD + col]       = __floats2half2_rn(cc[0], cc[1]);
            *(__half2*)&Gf[(size_t)(row + 8) * DD + col] = __floats2half2_rn(cc[2], cc[3]);
            if (i != j) {
                Gf[(size_t)col * DD + row]           = __float2half_rn(cc[0]);
                Gf[(size_t)(col + 1) * DD + row]     = __float2half_rn(cc[1]);
                Gf[(size_t)col * DD + row + 8]       = __float2half_rn(cc[2]);
                Gf[(size_t)(col + 1) * DD + row + 8] = __float2half_rn(cc[3]);
            }
        }
}

// ---------------- persistent kernel: 15 iterations + cleanup ----------------
// grid = 128 CTAs: f = bid>>5, n-word nt = bid&31 (32 d-columns). 512 threads = 16 warps.
// warp = (wm = w&3: 16 m-rows) x (kq = w>>2: 256-k quarter) x 32n. K-partials reduced via smem.
// smem: sG 128KB (1024k x 32n, stored in 64-wide swizzled rows, groups 0..3 used)
//       sBits 8KB | sCp 33KB partials
#define SM_BITS 131072
#define SM_CP   139264
#define SM_TOT  173056

__global__ void __launch_bounds__(512) k_run(float* __restrict__ out, int out_size) {
    extern __shared__ __align__(16) char smem[];
    __half* sG    = (__half*)smem;
    ull*    sBits = (ull*)(smem + SM_BITS);
    float*  sCp   = (float*)(smem + SM_CP);
    char*   aux   = smem + SM_BITS;

    int t = threadIdx.x, lane = t & 31, w = t >> 5;
    int wm = w & 3, kq = w >> 2;
    int f = blockIdx.x >> 5, nt = blockIdx.x & 31, n0 = nt << 5;

    // load resident G slice: 1024 rows x 32 cols into groups c8=0..3 of 64-wide swizzled rows
    {
        const __half* Gf = g_G + (size_t)f * DD * DD + n0;
        for (int idx = t; idx < 4096; idx += 512) {
            int r = idx >> 2, c8 = idx & 3;
            uint4 v = *(const uint4*)(Gf + (size_t)r * DD + c8 * 8);
            *(uint4*)(sG + r * 64 + ((c8 ^ (r & 7)) << 3)) = v;
        }
    }

    int lq = lane & 3, lh = lane >> 4, l15 = lane & 15;
    int r0 = wm * 16 + (lane >> 2), r1 = r0 + 8;
    int shb = lq * 2;

    for (int it = 0; it < NITER; it++) {
        int p = it & 1;
        const ull* E = g_est[p];

        // new_est bits: in ^ (xor of all est) ^ est_f
        for (int idx = t; idx < BB * WD; idx += 512) {
            int b = idx >> 4, wd = idx & 15;
            ull x = g_in[b * WD + wd];
            x ^= E[(b * FF + 0) * WD + wd] ^ E[(b * FF + 1) * WD + wd]
               ^ E[(b * FF + 2) * WD + wd] ^ E[(b * FF + 3) * WD + wd];
            sBits[idx] = x ^ E[(b * FF + f) * WD + wd];
        }
        __syncthreads();   // bits + (it=0) G-load visible

        float acc[4][4];
        #pragma unroll
        for (int a = 0; a < 4; a++)
            #pragma unroll
            for (int q = 0; q < 4; q++) acc[a][q] = 0.f;

        // sync-free mainloop: A fragments built in registers from bits, B from resident sG
        #pragma unroll
        for (int c4 = 0; c4 < 4; c4++) {
            int C = kq * 4 + c4;
            ull w0 = sBits[r0 * WD + C];
            ull w1 = sBits[r1 * WD + C];
            #pragma unroll
            for (int k16 = 0; k16 < 4; k16++) {
                int sh = k16 * 16 + shb;
                uint32_t t0 = (uint32_t)(w0 >> sh), t1 = (uint32_t)(w1 >> sh);
                uint32_t a0 = bexp(t0), a1 = bexp(t1);
                uint32_t a2 = bexp(t0 >> 8), a3 = bexp(t1 >> 8);
                int br = C * 64 + k16 * 16 + l15;
                uint32_t b0, b1, b2, b3;
                int bc8 = lh;
                ldm_x4_t(b0, b1, b2, b3, smem_u32(sG + br * 64 + ((bc8 ^ (br & 7)) << 3)));
                mma16816(acc[0], a0, a1, a2, a3, b0, b1);
                mma16816(acc[1], a0, a1, a2, a3, b2, b3);
                bc8 = 2 + lh;
                ldm_x4_t(b0, b1, b2, b3, smem_u32(sG + br * 64 + ((bc8 ^ (br & 7)) << 3)));
                mma16816(acc[2], a0, a1, a2, a3, b0, b1);
                mma16816(acc[3], a0, a1, a2, a3, b2, b3);
            }
        }

        // stage K-partials: sCp[kq][64][33]
        {
            float* P = sCp + kq * 2112;
            #pragma unroll
            for (int j = 0; j < 4; j++) {
                P[r0 * 33 + j * 8 + shb]       = acc[j][0];
                P[r0 * 33 + j * 8 + shb + 1]   = acc[j][1];
                P[r1 * 33 + j * 8 + shb]       = acc[j][2];
                P[r1 * 33 + j * 8 + shb + 1]   = acc[j][3];
            }
        }
        __syncthreads();

        // reduce 4 K-quarters, sign (sign(0)=+1 -> strict <0), pack u32, compare
        if (t < 64) {
            uint32_t word = 0;
            #pragma unroll
            for (int j = 0; j < 32; j++) {
                float s = sCp[t * 33 + j] + sCp[2112 + t * 33 + j]
                        + sCp[4224 + t * 33 + j] + sCp[6336 + t * 33 + j];
                word |= (uint32_t)(s < 0.f) << j;
            }
            int ei = (t * FF + f) * 32 + nt;
            uint32_t old = ((const uint32_t*)g_est[p])[ei];
            ((uint32_t*)g_est[p ^ 1])[ei] = word;
            unsigned msk = __ballot_sync(0xffffffffu, word != old);
            if (lane == 0 && msk) atomicAdd(&g_mismatch[it], __popc(msk));
        }

        grid_bar(it);
    }

    // ---------------- cleanup: argmax|sim| per (b, f), est floats, iters/conv ----------------
    {
        int f2 = blockIdx.x >> 5, bg = blockIdx.x & 31;   // 2 batches per CTA
        ull* sE = (ull*)aux;                              // 2 x 16 ull
        int* rA = (int*)(aux + 256);
        int* rI = (int*)(aux + 256 + 2048);
        const ull* Ef = g_est[NITER & 1];

        if (t < 32) {
            int j = t >> 4, wd = t & 15;
            sE[j * WD + wd] = Ef[(size_t)((bg * 2 + j) * FF + f2) * WD + wd];
        }
        __syncthreads();

        const ull* cb = g_cbD + (size_t)f2 * MM * WD;
        int bestA[2] = {-1, -1}, bestI[2] = {0, 0};
        for (int m = t; m < MM; m += 512) {
            ull rb[WD];
            const ull* rp = cb + (size_t)m * WD;
            #pragma unroll
            for (int q = 0; q < WD; q++) rb[q] = rp[q];
            #pragma unroll
            for (int j = 0; j < 2; j++) {
                int h = 0;
                #pragma unroll
                for (int q = 0; q < WD; q++) h += __popcll(rb[q] ^ sE[j * WD + q]);
                int s = DD - 2 * h;
                int a = s < 0 ? -s : s;
                if (a > bestA[j]) { bestA[j] = a; bestI[j] = m; }
            }
        }

        #pragma unroll
        for (int j = 0; j < 2; j++) {
            __syncthreads();
            rA[t] = bestA[j]; rI[t] = bestI[j];
            __syncthreads();
            for (int off = 256; off; off >>= 1) {
                if (t < off) {
                    int a2 = rA[t + off], i2 = rI[t + off];
                    if (a2 > rA[t] || (a2 == rA[t] && i2 < rI[t])) { rA[t] = a2; rI[t] = i2; }
                }
                __syncthreads();
            }
            int idx = (bg * 2 + j) * FF + f2;
            if (t == 0 && idx < out_size) out[idx] = (float)rI[0];
            if (out_size >= 256 + BB * FF * DD) {
                float* oe = out + 256 + (size_t)idx * DD;
                for (int d = t; d < DD; d += 512) {
                    int bit = (int)((sE[j * WD + (d >> 6)] >> (d & 63)) & 1ULL);
                    oe[d] = bit ? -1.f : 1.f;
                }
            }
        }

        if (blockIdx.x == 0 && t == 0 && out_size >= 256 + BB * FF * DD + 2) {
            int iters = NITER, conv = 0;
            for (int tt = 0; tt < NITER; tt++)
                if (g_mismatch[tt] == 0) { iters = tt + 1; conv = 1; break; }
            out[256 + BB * FF * DD]     = (float)iters;
            out[256 + BB * FF * DD + 1] = (float)conv;
        }
    }
}

// ---------------- launch ----------------
extern "C" void kernel_launch(void* const* d_in, const int* in_sizes, int n_in,
                              void* d_out, int out_size) {
    const float* input = nullptr;
    const float* est0  = nullptr;
    const float* cb    = nullptr;
    for (int i = 0; i < n_in; i++) {
        if (in_sizes[i] == BB * DD)            input = (const float*)d_in[i];
        else if (in_sizes[i] == BB * FF * DD)  est0  = (const float*)d_in[i];
        else if (in_sizes[i] == FF * MM * DD)  cb    = (const float*)d_in[i];
    }
    cudaFuncSetAttribute(k_run, cudaFuncAttributeMaxDynamicSharedMemorySize, SM_TOT);
    k_pack_est<<<80, 128>>>(input, est0);
    k_pack_cb<<<FF * MM / 4, 128>>>(cb);
    k_gram<<<FF * 36, 256>>>();
    k_run<<<GRID_RUN, 512, SM_TOT>>>((float*)d_out, out_size);
}